// round 8
// baseline (speedup 1.0000x reference)
#include <cuda_runtime.h>
#include <cstdint>

// delta_layer: out[b,t,:] = [ x, delta(x), delta(delta(x)) ]
// delta(y)[t] = 0.5*(y[c(t+1)]-y[c(t-1)]) + 0.25*(y[c(t+2)]-y[c(t-2)]), c = clamp [0,T-1]
// Shapes fixed: B=32, T=4096, D=256, window=2.
//
// Round-8: direction-batched bulk memory with BIGGER tiles.
//   1) ONE cp.async.bulk load  (24 KB: rows t0-4 .. t0+19, contiguous)
//   2) 256 threads compute 16 rows (each thread: 8 rows of one float2 column,
//      9-deep register ring fed from smem)
//   3) ONE cp.async.bulk store (48 KB: 16 output rows x 3KB, contiguous)
// Halo amplification 1.5x (vs 2x at L=8), half the per-tile fixed costs.
// Interior rows use the fused 9-tap double-delta:
//   dd(t) = 0.0625(x[t-4]+x[t+4]) + 0.25(x[t-3]+x[t+3]) + 0.25(x[t-2]+x[t+2])
//         - 0.25(x[t-1]+x[t+1]) - 0.625 x[t]

#define B_N 32
#define T_N 4096
#define F2_N 128            // float2 per input row (256 floats)
#define OF2_N 384           // float2 per output row (768 floats)
#define L_N 16              // rows per tile
#define CHUNKS (T_N / L_N)  // 256
#define IN_ROWS (L_N + 8)   // 24
#define IN_BYTES (IN_ROWS * F2_N * 8)   // 24576
#define OUT_BYTES (L_N * OF2_N * 8)     // 49152
#define SMEM_DYN (IN_BYTES + OUT_BYTES) // 73728

__device__ __forceinline__ uint32_t smem_u32(const void* p) {
    uint32_t a;
    asm("{ .reg .u64 t; cvta.to.shared.u64 t, %1; cvt.u32.u64 %0, t; }"
        : "=r"(a) : "l"(p));
    return a;
}

__device__ __forceinline__ float2 f2_delta(float2 m2, float2 m1, float2 p1, float2 p2) {
    float2 r;
    r.x = 0.5f * (p1.x - m1.x) + 0.25f * (p2.x - m2.x);
    r.y = 0.5f * (p1.y - m1.y) + 0.25f * (p2.y - m2.y);
    return r;
}

__device__ __forceinline__ float dd9(float a0, float a1, float a2, float a3, float a4,
                                     float a5, float a6, float a7, float a8) {
    return 0.0625f * (a0 + a8) + 0.25f * (a1 + a7) + 0.25f * (a2 + a6)
         - 0.25f * (a3 + a5) - 0.625f * a4;
}

__global__ void __launch_bounds__(256, 3)
delta_layer_kernel(const float2* __restrict__ x, float2* __restrict__ out) {
    extern __shared__ float2 sdyn[];              // [IN_ROWS*F2_N] then [L_N*OF2_N]
    __shared__ alignas(8) unsigned long long mbar_s;

    float2* s_in  = sdyn;
    float2* s_out = sdyn + IN_ROWS * F2_N;

    const int tid   = threadIdx.x;                 // 0..255
    const int col   = tid & (F2_N - 1);            // float2 column 0..127
    const int half  = tid >> 7;                    // 0 or 1 -> rows [half*8, half*8+8)
    const int chunk = blockIdx.x;                  // 0..255
    const int b     = blockIdx.y;
    const int t0    = chunk * L_N;

    if (chunk != 0 && chunk != CHUNKS - 1) {
        // ---------------- interior: bulk load -> ring compute -> bulk store ----
        const uint32_t mbar   = smem_u32(&mbar_s);
        const uint32_t sin_a  = smem_u32(s_in);
        const uint32_t sout_a = smem_u32(s_out);

        if (tid == 0) {
            asm volatile("mbarrier.init.shared.b64 [%0], 1;" :: "r"(mbar) : "memory");
        }
        __syncthreads();
        if (tid == 0) {
            asm volatile("mbarrier.arrive.expect_tx.shared.b64 _, [%0], %1;"
                         :: "r"(mbar), "r"((uint32_t)IN_BYTES) : "memory");
            const float2* src = x + ((size_t)b * T_N + (t0 - 4)) * F2_N;
            asm volatile(
                "cp.async.bulk.shared::cluster.global.mbarrier::complete_tx::bytes "
                "[%0], [%1], %2, [%3];"
                :: "r"(sin_a), "l"(src), "r"((uint32_t)IN_BYTES), "r"(mbar) : "memory");
        }
        // wait for the bulk load (phase 0)
        asm volatile(
            "{\n\t.reg .pred P;\n\t"
            "W%=: mbarrier.try_wait.parity.shared::cta.b64 P, [%0], 0;\n\t"
            "@!P bra W%=;\n\t}"
            :: "r"(mbar) : "memory");

        // thread computes local rows lr = half*8 .. half*8+7
        // ring r[j] = smem input row (lr + j), j=0..8  (global row t0-4+lr+j)
        const float2* inp = s_in + col;
        const int lr0 = half * 8;
        float2 r[9];
#pragma unroll
        for (int j = 0; j < 9; ++j) r[j] = inp[(lr0 + j) * F2_N];

#pragma unroll
        for (int i = 0; i < 8; ++i) {
            const int lr = lr0 + i;
            float2* orow = s_out + lr * OF2_N + col;
            orow[0]        = r[4];                             // x
            orow[F2_N]     = f2_delta(r[2], r[3], r[5], r[6]); // delta
            float2 dd;
            dd.x = dd9(r[0].x, r[1].x, r[2].x, r[3].x, r[4].x, r[5].x, r[6].x, r[7].x, r[8].x);
            dd.y = dd9(r[0].y, r[1].y, r[2].y, r[3].y, r[4].y, r[5].y, r[6].y, r[7].y, r[8].y);
            orow[2 * F2_N] = dd;                               // double delta

            if (i < 7) {
#pragma unroll
                for (int j = 0; j < 8; ++j) r[j] = r[j + 1];
                r[8] = inp[(lr0 + i + 9) * F2_N];              // max index 23 (= IN_ROWS-1)
            }
        }
        __syncthreads();

        if (tid == 0) {
            asm volatile("fence.proxy.async.shared::cta;" ::: "memory");
            float2* dst = out + ((size_t)b * T_N + t0) * OF2_N;
            asm volatile(
                "cp.async.bulk.global.shared::cta.bulk_group [%0], [%1], %2;"
                :: "l"(dst), "r"(sout_a), "r"((uint32_t)OUT_BYTES) : "memory");
            asm volatile("cp.async.bulk.commit_group;" ::: "memory");
            asm volatile("cp.async.bulk.wait_group 0;" ::: "memory");
        }
    } else {
        // ---------------- edge path: generic clamped math, direct global ------
        const float2* __restrict__ xb = x   + (size_t)b * T_N * F2_N  + col;
        float2*       __restrict__ ob = out + (size_t)b * T_N * OF2_N + col;

        auto LD = [&](int t) -> float2 {
            t = t < 0 ? 0 : (t > T_N - 1 ? T_N - 1 : t);
            return __ldg(xb + (size_t)t * F2_N);
        };
        auto DELTA_AT = [&](int sdx) -> float2 {
            sdx = sdx < 0 ? 0 : (sdx > T_N - 1 ? T_N - 1 : sdx);
            return f2_delta(LD(sdx - 2), LD(sdx - 1), LD(sdx + 1), LD(sdx + 2));
        };

        for (int i = 0; i < 8; ++i) {
            const int t = t0 + half * 8 + i;
            const size_t orow = (size_t)t * OF2_N;
            ob[orow]            = LD(t);
            ob[orow + F2_N]     = DELTA_AT(t);
            ob[orow + 2 * F2_N] =
                f2_delta(DELTA_AT(t - 2), DELTA_AT(t - 1), DELTA_AT(t + 1), DELTA_AT(t + 2));
        }
    }
}

extern "C" void kernel_launch(void* const* d_in, const int* in_sizes, int n_in,
                              void* d_out, int out_size) {
    const float2* x = (const float2*)d_in[0];
    float2* out     = (float2*)d_out;
    // d_in[1] = window (always 2) — baked in.

    static bool attr_set = false;
    if (!attr_set) {
        cudaFuncSetAttribute(delta_layer_kernel,
                             cudaFuncAttributeMaxDynamicSharedMemorySize, SMEM_DYN);
        attr_set = true;
    }

    dim3 block(256, 1);
    dim3 grid(CHUNKS, B_N);   // (256, 32) = 8192 blocks
    delta_layer_kernel<<<grid, block, SMEM_DYN>>>(x, out);
}

// round 9
// speedup vs baseline: 1.0430x; 1.0430x over previous
#include <cuda_runtime.h>
#include <cstdint>

// delta_layer: out[b,t,:] = [ x, delta(x), delta(delta(x)) ]
// delta(y)[t] = 0.5*(y[c(t+1)]-y[c(t-1)]) + 0.25*(y[c(t+2)]-y[c(t-2)]), c = clamp [0,T-1]
// Shapes fixed: B=32, T=4096, D=256, window=2.
//
// Round-9: hybrid. Reads: per-thread 9-deep float2 register ring via __ldg
// (L1/L2 absorb the halo; read path proven non-binding). Writes: staged in a
// 24KB smem tile and issued as ONE cp.async.bulk store (the round-7 active
// ingredient: long same-direction write bursts). 24KB smem -> 9 blocks/SM,
// ~2x the concurrently outstanding bulk stores vs round 7.
// Interior rows use the fused 9-tap double-delta:
//   dd(t) = 0.0625(x[t-4]+x[t+4]) + 0.25(x[t-3]+x[t+3]) + 0.25(x[t-2]+x[t+2])
//         - 0.25(x[t-1]+x[t+1]) - 0.625 x[t]

#define B_N 32
#define T_N 4096
#define F2_N 128            // float2 per input row (256 floats)
#define OF2_N 384           // float2 per output row (768 floats)
#define L_N 8               // rows per tile
#define CHUNKS (T_N / L_N)  // 512
#define OUT_BYTES (L_N * OF2_N * 8)   // 24576

__device__ __forceinline__ uint32_t smem_u32(const void* p) {
    uint32_t a;
    asm("{ .reg .u64 t; cvta.to.shared.u64 t, %1; cvt.u32.u64 %0, t; }"
        : "=r"(a) : "l"(p));
    return a;
}

__device__ __forceinline__ float2 f2_delta(float2 m2, float2 m1, float2 p1, float2 p2) {
    float2 r;
    r.x = 0.5f * (p1.x - m1.x) + 0.25f * (p2.x - m2.x);
    r.y = 0.5f * (p1.y - m1.y) + 0.25f * (p2.y - m2.y);
    return r;
}

__device__ __forceinline__ float dd9(float a0, float a1, float a2, float a3, float a4,
                                     float a5, float a6, float a7, float a8) {
    return 0.0625f * (a0 + a8) + 0.25f * (a1 + a7) + 0.25f * (a2 + a6)
         - 0.25f * (a3 + a5) - 0.625f * a4;
}

__global__ void __launch_bounds__(128, 9)
delta_layer_kernel(const float2* __restrict__ x, float2* __restrict__ out) {
    __shared__ alignas(128) float2 s_out[L_N * OF2_N];   // 24 KB output staging

    const int tid   = threadIdx.x;           // 0..127 = float2 channel column
    const int chunk = blockIdx.x;             // 0..511
    const int b     = blockIdx.y;
    const int t0    = chunk * L_N;

    const float2* __restrict__ xb = x + (size_t)b * T_N * F2_N + tid;

    if (chunk != 0 && chunk != CHUNKS - 1) {
        // ---- interior: __ldg register ring -> smem tile -> ONE bulk store ----
        // ring r[j] = x[t0-4+j], all in-bounds for interior chunks
        float2 r[9];
#pragma unroll
        for (int j = 0; j < 9; ++j)
            r[j] = __ldg(xb + (size_t)(t0 - 4 + j) * F2_N);

#pragma unroll
        for (int i = 0; i < L_N; ++i) {
            float2* orow = s_out + i * OF2_N + tid;
            orow[0]        = r[4];                             // x
            orow[F2_N]     = f2_delta(r[2], r[3], r[5], r[6]); // delta
            float2 dd;
            dd.x = dd9(r[0].x, r[1].x, r[2].x, r[3].x, r[4].x, r[5].x, r[6].x, r[7].x, r[8].x);
            dd.y = dd9(r[0].y, r[1].y, r[2].y, r[3].y, r[4].y, r[5].y, r[6].y, r[7].y, r[8].y);
            orow[2 * F2_N] = dd;                               // double delta

            if (i < L_N - 1) {
#pragma unroll
                for (int j = 0; j < 8; ++j) r[j] = r[j + 1];
                // max index: t0+4+8 = t0+12 <= 4092 < T for interior chunks
                r[8] = __ldg(xb + (size_t)(t0 + 5 + i) * F2_N);
            }
        }
        __syncthreads();

        if (tid == 0) {
            asm volatile("fence.proxy.async.shared::cta;" ::: "memory");
            float2* dst = out + ((size_t)b * T_N + t0) * OF2_N;
            asm volatile(
                "cp.async.bulk.global.shared::cta.bulk_group [%0], [%1], %2;"
                :: "l"(dst), "r"(smem_u32(s_out)), "r"((uint32_t)OUT_BYTES) : "memory");
            asm volatile("cp.async.bulk.commit_group;" ::: "memory");
            asm volatile("cp.async.bulk.wait_group 0;" ::: "memory");
        }
    } else {
        // ---- edge path: generic clamped math, direct global stores ----
        float2* __restrict__ ob = out + (size_t)b * T_N * OF2_N + tid;

        auto LD = [&](int t) -> float2 {
            t = t < 0 ? 0 : (t > T_N - 1 ? T_N - 1 : t);
            return __ldg(xb + (size_t)t * F2_N);
        };
        auto DELTA_AT = [&](int sdx) -> float2 {
            sdx = sdx < 0 ? 0 : (sdx > T_N - 1 ? T_N - 1 : sdx);
            return f2_delta(LD(sdx - 2), LD(sdx - 1), LD(sdx + 1), LD(sdx + 2));
        };

        for (int i = 0; i < L_N; ++i) {
            const int t = t0 + i;
            const size_t orow = (size_t)t * OF2_N;
            ob[orow]            = LD(t);
            ob[orow + F2_N]     = DELTA_AT(t);
            ob[orow + 2 * F2_N] =
                f2_delta(DELTA_AT(t - 2), DELTA_AT(t - 1), DELTA_AT(t + 1), DELTA_AT(t + 2));
        }
    }
}

extern "C" void kernel_launch(void* const* d_in, const int* in_sizes, int n_in,
                              void* d_out, int out_size) {
    const float2* x = (const float2*)d_in[0];
    float2* out     = (float2*)d_out;
    // d_in[1] = window (always 2) — baked in.

    dim3 block(128, 1);
    dim3 grid(CHUNKS, B_N);   // (512, 32) = 16384 blocks
    delta_layer_kernel<<<grid, block>>>(x, out);
}